// round 8
// baseline (speedup 1.0000x reference)
#include <cuda_runtime.h>
#include <cuda_bf16.h>
#include <cstdint>

// ---------------------------------------------------------------------------
// Problem shape (fixed by the dataset)
// ---------------------------------------------------------------------------
#define BB 8
#define MM 2048
#define NN 2048
#define KK 2048
#define T64 64
#define MT 32
#define KT 32
#define THRESH 1e-6f

// ---------------------------------------------------------------------------
// Scratch (device globals — no allocation allowed)
// ---------------------------------------------------------------------------
__device__ __nv_bfloat16 g_Ahi[(size_t)BB * MM * KK];   // [b][m][k]
__device__ __nv_bfloat16 g_Alo[(size_t)BB * MM * KK];
__device__ __nv_bfloat16 g_Bhi[(size_t)BB * NN * KK];   // transposed: [b][n][k]
__device__ __nv_bfloat16 g_Blo[(size_t)BB * NN * KK];

// ---------------------------------------------------------------------------
// Helpers
// ---------------------------------------------------------------------------
__device__ __forceinline__ uint32_t smem_u32(const void* p) {
    uint32_t a;
    asm("{ .reg .u64 t; cvta.to.shared.u64 t, %1; cvt.u32.u64 %0, t; }" : "=r"(a) : "l"(p));
    return a;
}
__device__ __forceinline__ void cp16(uint32_t dst, const void* src) {
    asm volatile("cp.async.cg.shared.global [%0], [%1], 16;" :: "r"(dst), "l"(src));
}
// 64-byte-row swizzle (SW64): XOR bits[5:4] with bits[8:7]
#define SMEM_SWIZZLE_64B(off) ((off) ^ (((off) >> 3) & 0x30))

__device__ __forceinline__ void ldsm_x4(uint32_t r[4], uint32_t addr) {
    asm volatile("ldmatrix.sync.aligned.m8n8.x4.shared.b16 {%0,%1,%2,%3}, [%4];"
                 : "=r"(r[0]), "=r"(r[1]), "=r"(r[2]), "=r"(r[3]) : "r"(addr));
}
__device__ __forceinline__ void mma_bf16(float c[4], const uint32_t a[4],
                                         uint32_t b0, uint32_t b1) {
    asm volatile(
        "mma.sync.aligned.m16n8k16.row.col.f32.bf16.bf16.f32 "
        "{%0,%1,%2,%3}, {%4,%5,%6,%7}, {%8,%9}, {%0,%1,%2,%3};"
        : "+f"(c[0]), "+f"(c[1]), "+f"(c[2]), "+f"(c[3])
        : "r"(a[0]), "r"(a[1]), "r"(a[2]), "r"(a[3]), "r"(b0), "r"(b1));
}

// ---------------------------------------------------------------------------
// Kernel 1: fused activity prescan + A conversion.
//   One block per 64x64 tile: load tile to regs, block max-reduce |a|,
//   then mask + bf16 hi/lo split + store.  Reads A exactly once.
// ---------------------------------------------------------------------------
__global__ __launch_bounds__(256)
void convA_fused_kernel(const float* __restrict__ a) {
    const int tile = blockIdx.x;
    const int b    = tile / (MT * KT);
    const int rem  = tile % (MT * KT);
    const int mt   = rem / KT;
    const int kt   = rem % KT;
    const size_t gbase = ((size_t)b * MM + (size_t)mt * T64) * KK + (size_t)kt * T64;
    const float* base = a + gbase;

    const int r0 = threadIdx.x >> 4;          // 0..15
    const int c0 = (threadIdx.x & 15) * 4;    // 0..60

    float4 v[4];
    float mx = 0.0f;
    #pragma unroll
    for (int j = 0; j < 4; j++) {
        v[j] = *reinterpret_cast<const float4*>(base + (size_t)(r0 + j * 16) * KK + c0);
        mx = fmaxf(mx, fmaxf(fmaxf(fabsf(v[j].x), fabsf(v[j].y)),
                             fmaxf(fabsf(v[j].z), fabsf(v[j].w))));
    }
    #pragma unroll
    for (int off = 16; off > 0; off >>= 1)
        mx = fmaxf(mx, __shfl_xor_sync(0xFFFFFFFFu, mx, off));

    __shared__ float s[8];
    __shared__ float s_msk;
    if ((threadIdx.x & 31) == 0) s[threadIdx.x >> 5] = mx;
    __syncthreads();
    if (threadIdx.x == 0) {
        float m = s[0];
        #pragma unroll
        for (int w = 1; w < 8; w++) m = fmaxf(m, s[w]);
        s_msk = (m > THRESH) ? 1.0f : 0.0f;
    }
    __syncthreads();
    const float msk = s_msk;

    #pragma unroll
    for (int j = 0; j < 4; j++) {
        float f[4] = {v[j].x * msk, v[j].y * msk, v[j].z * msk, v[j].w * msk};
        unsigned short hb[4], lb[4];
        #pragma unroll
        for (int q = 0; q < 4; q++) {
            __nv_bfloat16 h = __float2bfloat16_rn(f[q]);
            __nv_bfloat16 l = __float2bfloat16_rn(f[q] - __bfloat162float(h));
            hb[q] = *reinterpret_cast<unsigned short*>(&h);
            lb[q] = *reinterpret_cast<unsigned short*>(&l);
        }
        const size_t o = gbase + (size_t)(r0 + j * 16) * KK + c0;
        *reinterpret_cast<ushort4*>(g_Ahi + o) = make_ushort4(hb[0], hb[1], hb[2], hb[3]);
        *reinterpret_cast<ushort4*>(g_Alo + o) = make_ushort4(lb[0], lb[1], lb[2], lb[3]);
    }
}

// ---------------------------------------------------------------------------
// Kernel 2: convert + transpose B: fp32 [b][k][n] -> bf16 hi/lo [b][n][k]
//   float4 gmem loads, conflict-free padded-smem transpose, ushort4 stores.
// ---------------------------------------------------------------------------
__global__ __launch_bounds__(256)
void convB_kernel(const float* __restrict__ Bsrc) {
    __shared__ float t[32][33];
    const int b  = blockIdx.z;
    const int n0 = blockIdx.x * 32;
    const int k0 = blockIdx.y * 32;
    const int tid = threadIdx.x;

    // load 32x32 fp32 tile: each thread one float4
    {
        const int r  = tid >> 3;            // 0..31 (k-row)
        const int c4 = (tid & 7) * 4;       // n offset
        const float4 v = *reinterpret_cast<const float4*>(
            Bsrc + (size_t)b * KK * NN + (size_t)(k0 + r) * NN + n0 + c4);
        t[r][c4 + 0] = v.x; t[r][c4 + 1] = v.y;
        t[r][c4 + 2] = v.z; t[r][c4 + 3] = v.w;
    }
    __syncthreads();

    // store transposed: each thread handles 4 consecutive k for one n
    const int n  = tid >> 3;                // 0..31
    const int kg = (tid & 7) * 4;           // 0..28
    unsigned short hb[4], lb[4];
    #pragma unroll
    for (int j = 0; j < 4; j++) {
        const float v = t[kg + j][n];       // stride-33 column read: conflict-free
        __nv_bfloat16 h = __float2bfloat16_rn(v);
        __nv_bfloat16 l = __float2bfloat16_rn(v - __bfloat162float(h));
        hb[j] = *reinterpret_cast<unsigned short*>(&h);
        lb[j] = *reinterpret_cast<unsigned short*>(&l);
    }
    const size_t o = (size_t)b * NN * KK + (size_t)(n0 + n) * KK + k0 + kg;
    *reinterpret_cast<ushort4*>(g_Bhi + o) = make_ushort4(hb[0], hb[1], hb[2], hb[3]);
    *reinterpret_cast<ushort4*>(g_Blo + o) = make_ushort4(lb[0], lb[1], lb[2], lb[3]);
}

// ---------------------------------------------------------------------------
// Kernel 3: bf16 split-3 GEMM via mma.sync (m16n8k16).
//   CTA tile 128(M) x 128(N), K-chunk 32, 8 warps (2x4), warp tile 64x32.
//   3 buffers / prefetch-depth-2 cp.async pipeline, ONE barrier per iteration.
// ---------------------------------------------------------------------------
#define GM 128
#define GN 128
#define GK 32
#define KCHUNKS (KK / GK)            // 64
#define NSTAGE 3

// Stage layout (SW64-swizzled 64-byte rows):
//   AHI [128][64B], ALO [128][64B], BHI [128][64B], BLO [128][64B]
#define OFF_AHI 0
#define OFF_ALO 8192
#define OFF_BHI 16384
#define OFF_BLO 24576
#define STAGE_BYTES 32768            // 32 KB
#define GEMM_SMEM (NSTAGE * STAGE_BYTES)  // 96 KB

__device__ __forceinline__ void load_stage(uint32_t sbase,
                                           const __nv_bfloat16* Ah, const __nv_bfloat16* Al,
                                           const __nv_bfloat16* Bh, const __nv_bfloat16* Bl,
                                           int k0, int tid) {
    // each array: 128 rows x 4 x 16B chunks = 512 chunks; 2 per thread per array
    #pragma unroll
    for (int t = 0; t < 2; t++) {
        const int c = tid + t * 256;
        const int r = c >> 2, kc = c & 3;
        const uint32_t off = SMEM_SWIZZLE_64B((uint32_t)(r * 64 + kc * 16));
        const size_t gofs = (size_t)r * KK + k0 + kc * 8;    // bf16 elements
        cp16(sbase + OFF_AHI + off, Ah + gofs);
        cp16(sbase + OFF_ALO + off, Al + gofs);
        cp16(sbase + OFF_BHI + off, Bh + gofs);
        cp16(sbase + OFF_BLO + off, Bl + gofs);
    }
}

__global__ __launch_bounds__(256, 2)
void gemm_kernel(float* __restrict__ C) {
    extern __shared__ __align__(1024) char smem[];
    const uint32_t sb = smem_u32(smem);
    const int tid  = threadIdx.x;
    const int wid  = tid >> 5;
    const int lane = tid & 31;
    const int wm   = wid >> 2;           // 0..1  -> m offset wm*64
    const int wn   = wid & 3;            // 0..3  -> n offset wn*32
    const int b  = blockIdx.z;
    const int m0 = blockIdx.y * GM;
    const int n0 = blockIdx.x * GN;

    const __nv_bfloat16* Ah = g_Ahi + (size_t)b * MM * KK + (size_t)m0 * KK;
    const __nv_bfloat16* Al = g_Alo + (size_t)b * MM * KK + (size_t)m0 * KK;
    const __nv_bfloat16* Bh = g_Bhi + (size_t)b * NN * KK + (size_t)n0 * KK;
    const __nv_bfloat16* Bl = g_Blo + (size_t)b * NN * KK + (size_t)n0 * KK;

    float acc[4][4][4];                  // [m-tile][n-tile][frag]
    #pragma unroll
    for (int i = 0; i < 4; i++)
        #pragma unroll
        for (int j = 0; j < 4; j++)
            #pragma unroll
            for (int r = 0; r < 4; r++) acc[i][j][r] = 0.0f;

    const int lrow  = lane & 15;
    const int lhalf = lane >> 4;         // 0/1 -> +0 / +8 k-elements (16B)

    // prologue: prefetch depth 2 (chunks 0 and 1)
    load_stage(sb + 0 * STAGE_BYTES, Ah, Al, Bh, Bl, 0 * GK, tid);
    asm volatile("cp.async.commit_group;" ::: "memory");
    load_stage(sb + 1 * STAGE_BYTES, Ah, Al, Bh, Bl, 1 * GK, tid);
    asm volatile("cp.async.commit_group;" ::: "memory");

    int stage = 0;           // slot of chunk `it`  (chunk c -> slot c % 3)
    int fill  = 2;           // slot of chunk `it+2` (computed at it-1; free after barrier)
    for (int it = 0; it < KCHUNKS; it++) {
        const uint32_t sbase = sb + stage * STAGE_BYTES;

        // chunk `it` must be resident; chunk `it+1` may still be in flight
        if (it + 2 < KCHUNKS) asm volatile("cp.async.wait_group 1;" ::: "memory");
        else                  asm volatile("cp.async.wait_group 0;" ::: "memory");
        // single joint barrier: data-ready for all warps AND all warps done
        // reading slot `fill` (they read it as chunk it-1 last iteration)
        __syncthreads();

        // issue next load FIRST: full compute window to cover it
        if (it + 2 < KCHUNKS) {
            load_stage(sb + fill * STAGE_BYTES, Ah, Al, Bh, Bl, (it + 2) * GK, tid);
            asm volatile("cp.async.commit_group;" ::: "memory");
        }

        #pragma unroll
        for (int ks = 0; ks < 2; ks++) {     // 2 x k16 steps per 32-chunk
            const uint32_t bytecol = (uint32_t)(ks * 32 + lhalf * 16);

            uint32_t ahi[4][4], alo[4][4], bb[2][4];
            #pragma unroll
            for (int mt = 0; mt < 4; mt++) {
                const uint32_t off = SMEM_SWIZZLE_64B(
                    (uint32_t)((wm * 64 + mt * 16 + lrow) * 64) + bytecol);
                ldsm_x4(ahi[mt], sbase + OFF_AHI + off);
                ldsm_x4(alo[mt], sbase + OFF_ALO + off);
            }
            #pragma unroll
            for (int nt2 = 0; nt2 < 2; nt2++) {
                const uint32_t off = SMEM_SWIZZLE_64B(
                    (uint32_t)((wn * 32 + nt2 * 16 + lrow) * 64) + bytecol);
                ldsm_x4(bb[nt2], sbase + OFF_BHI + off);
            }

            // product 1: Ahi * Bhi   (16 MMAs, 16 distinct accumulators)
            #pragma unroll
            for (int mt = 0; mt < 4; mt++)
                #pragma unroll
                for (int nt2 = 0; nt2 < 2; nt2++) {
                    mma_bf16(acc[mt][nt2 * 2 + 0], ahi[mt], bb[nt2][0], bb[nt2][2]);
                    mma_bf16(acc[mt][nt2 * 2 + 1], ahi[mt], bb[nt2][1], bb[nt2][3]);
                }
            // product 2: Alo * Bhi
            #pragma unroll
            for (int mt = 0; mt < 4; mt++)
                #pragma unroll
                for (int nt2 = 0; nt2 < 2; nt2++) {
                    mma_bf16(acc[mt][nt2 * 2 + 0], alo[mt], bb[nt2][0], bb[nt2][2]);
                    mma_bf16(acc[mt][nt2 * 2 + 1], alo[mt], bb[nt2][1], bb[nt2][3]);
                }
            // reload B fragments with Blo (reuse registers)
            #pragma unroll
            for (int nt2 = 0; nt2 < 2; nt2++) {
                const uint32_t off = SMEM_SWIZZLE_64B(
                    (uint32_t)((wn * 32 + nt2 * 16 + lrow) * 64) + bytecol);
                ldsm_x4(bb[nt2], sbase + OFF_BLO + off);
            }
            // product 3: Ahi * Blo
            #pragma unroll
            for (int mt = 0; mt < 4; mt++)
                #pragma unroll
                for (int nt2 = 0; nt2 < 2; nt2++) {
                    mma_bf16(acc[mt][nt2 * 2 + 0], ahi[mt], bb[nt2][0], bb[nt2][2]);
                    mma_bf16(acc[mt][nt2 * 2 + 1], ahi[mt], bb[nt2][1], bb[nt2][3]);
                }
        }

        stage = (stage + 1 == NSTAGE) ? 0 : stage + 1;
        fill  = (fill  + 1 == NSTAGE) ? 0 : fill  + 1;
    }

    // epilogue: c frag -> rows (lane>>2) and +8, cols (lane&3)*2..+1
    const int crow0 = m0 + wm * 64 + (lane >> 2);
    const int ccol0 = n0 + wn * 32 + (lane & 3) * 2;
    float* Cb = C + (size_t)b * MM * NN;
    #pragma unroll
    for (int mt = 0; mt < 4; mt++) {
        #pragma unroll
        for (int nt = 0; nt < 4; nt++) {
            float* p0 = Cb + (size_t)(crow0 + mt * 16) * NN + ccol0 + nt * 8;
            float* p1 = p0 + 8 * NN;
            *reinterpret_cast<float2*>(p0) = make_float2(acc[mt][nt][0], acc[mt][nt][1]);
            *reinterpret_cast<float2*>(p1) = make_float2(acc[mt][nt][2], acc[mt][nt][3]);
        }
    }
}

// ---------------------------------------------------------------------------
// Launch
// ---------------------------------------------------------------------------
extern "C" void kernel_launch(void* const* d_in, const int* in_sizes, int n_in,
                              void* d_out, int out_size) {
    const float* a = (const float*)d_in[0];
    const float* bsrc = (const float*)d_in[1];
    float* out = (float*)d_out;

    cudaFuncSetAttribute(gemm_kernel, cudaFuncAttributeMaxDynamicSharedMemorySize, GEMM_SMEM);

    convA_fused_kernel<<<BB * MT * KT, 256>>>(a);
    dim3 gb(NN / 32, KK / 32, BB);          // (64, 64, 8)
    convB_kernel<<<gb, 256>>>(bsrc);
    dim3 gg(NN / GN, MM / GM, BB);          // (16, 16, 8)
    gemm_kernel<<<gg, 256, GEMM_SMEM>>>(out);
}

// round 9
// speedup vs baseline: 1.4274x; 1.4274x over previous
#include <cuda_runtime.h>
#include <cuda_fp16.h>
#include <cstdint>

// ---------------------------------------------------------------------------
// Problem shape (fixed by the dataset)
// ---------------------------------------------------------------------------
#define BB 8
#define MM 2048
#define NN 2048
#define KK 2048
#define T64 64
#define MT 32
#define KT 32
#define THRESH 1e-6f

// ---------------------------------------------------------------------------
// Scratch (device globals — no allocation allowed)
//   fp16 split-2: A = Ahi + Alo (22 mantissa bits), B = Bh (one fp16, RN)
// ---------------------------------------------------------------------------
__device__ __half g_Ahi[(size_t)BB * MM * KK];   // [b][m][k]
__device__ __half g_Alo[(size_t)BB * MM * KK];
__device__ __half g_Bh [(size_t)BB * NN * KK];   // transposed: [b][n][k]

// ---------------------------------------------------------------------------
// Helpers
// ---------------------------------------------------------------------------
__device__ __forceinline__ uint32_t smem_u32(const void* p) {
    uint32_t a;
    asm("{ .reg .u64 t; cvta.to.shared.u64 t, %1; cvt.u32.u64 %0, t; }" : "=r"(a) : "l"(p));
    return a;
}
__device__ __forceinline__ void cp16(uint32_t dst, const void* src) {
    asm volatile("cp.async.cg.shared.global [%0], [%1], 16;" :: "r"(dst), "l"(src));
}
// 64-byte-row swizzle (SW64): XOR bits[5:4] with bits[8:7]
#define SMEM_SWIZZLE_64B(off) ((off) ^ (((off) >> 3) & 0x30))

__device__ __forceinline__ void ldsm_x4(uint32_t r[4], uint32_t addr) {
    asm volatile("ldmatrix.sync.aligned.m8n8.x4.shared.b16 {%0,%1,%2,%3}, [%4];"
                 : "=r"(r[0]), "=r"(r[1]), "=r"(r[2]), "=r"(r[3]) : "r"(addr));
}
__device__ __forceinline__ void mma_f16(float c[4], const uint32_t a[4],
                                        uint32_t b0, uint32_t b1) {
    asm volatile(
        "mma.sync.aligned.m16n8k16.row.col.f32.f16.f16.f32 "
        "{%0,%1,%2,%3}, {%4,%5,%6,%7}, {%8,%9}, {%0,%1,%2,%3};"
        : "+f"(c[0]), "+f"(c[1]), "+f"(c[2]), "+f"(c[3])
        : "r"(a[0]), "r"(a[1]), "r"(a[2]), "r"(a[3]), "r"(b0), "r"(b1));
}

// ---------------------------------------------------------------------------
// Kernel 1: fused activity prescan + A conversion (fp16 hi/lo split).
//   One block per 64x64 tile: load tile to regs, block max-reduce |a|,
//   then mask + split + store.  Reads A exactly once.
// ---------------------------------------------------------------------------
__global__ __launch_bounds__(256)
void convA_fused_kernel(const float* __restrict__ a) {
    const int tile = blockIdx.x;
    const int b    = tile / (MT * KT);
    const int rem  = tile % (MT * KT);
    const int mt   = rem / KT;
    const int kt   = rem % KT;
    const size_t gbase = ((size_t)b * MM + (size_t)mt * T64) * KK + (size_t)kt * T64;
    const float* base = a + gbase;

    const int r0 = threadIdx.x >> 4;          // 0..15
    const int c0 = (threadIdx.x & 15) * 4;    // 0..60

    float4 v[4];
    float mx = 0.0f;
    #pragma unroll
    for (int j = 0; j < 4; j++) {
        v[j] = *reinterpret_cast<const float4*>(base + (size_t)(r0 + j * 16) * KK + c0);
        mx = fmaxf(mx, fmaxf(fmaxf(fabsf(v[j].x), fabsf(v[j].y)),
                             fmaxf(fabsf(v[j].z), fabsf(v[j].w))));
    }
    #pragma unroll
    for (int off = 16; off > 0; off >>= 1)
        mx = fmaxf(mx, __shfl_xor_sync(0xFFFFFFFFu, mx, off));

    __shared__ float s[8];
    __shared__ float s_msk;
    if ((threadIdx.x & 31) == 0) s[threadIdx.x >> 5] = mx;
    __syncthreads();
    if (threadIdx.x == 0) {
        float m = s[0];
        #pragma unroll
        for (int w = 1; w < 8; w++) m = fmaxf(m, s[w]);
        s_msk = (m > THRESH) ? 1.0f : 0.0f;
    }
    __syncthreads();
    const float msk = s_msk;

    #pragma unroll
    for (int j = 0; j < 4; j++) {
        float f[4] = {v[j].x * msk, v[j].y * msk, v[j].z * msk, v[j].w * msk};
        unsigned short hb[4], lb[4];
        #pragma unroll
        for (int q = 0; q < 4; q++) {
            __half h = __float2half_rn(f[q]);
            __half l = __float2half_rn(f[q] - __half2float(h));
            hb[q] = __half_as_ushort(h);
            lb[q] = __half_as_ushort(l);
        }
        const size_t o = gbase + (size_t)(r0 + j * 16) * KK + c0;
        *reinterpret_cast<ushort4*>(g_Ahi + o) = make_ushort4(hb[0], hb[1], hb[2], hb[3]);
        *reinterpret_cast<ushort4*>(g_Alo + o) = make_ushort4(lb[0], lb[1], lb[2], lb[3]);
    }
}

// ---------------------------------------------------------------------------
// Kernel 2: convert + transpose B: fp32 [b][k][n] -> fp16 [b][n][k]
//   float4 gmem loads, conflict-free padded-smem transpose, ushort4 stores.
// ---------------------------------------------------------------------------
__global__ __launch_bounds__(256)
void convB_kernel(const float* __restrict__ Bsrc) {
    __shared__ float t[32][33];
    const int b  = blockIdx.z;
    const int n0 = blockIdx.x * 32;
    const int k0 = blockIdx.y * 32;
    const int tid = threadIdx.x;

    // load 32x32 fp32 tile: each thread one float4
    {
        const int r  = tid >> 3;            // 0..31 (k-row)
        const int c4 = (tid & 7) * 4;       // n offset
        const float4 v = *reinterpret_cast<const float4*>(
            Bsrc + (size_t)b * KK * NN + (size_t)(k0 + r) * NN + n0 + c4);
        t[r][c4 + 0] = v.x; t[r][c4 + 1] = v.y;
        t[r][c4 + 2] = v.z; t[r][c4 + 3] = v.w;
    }
    __syncthreads();

    // store transposed: each thread handles 4 consecutive k for one n
    const int n  = tid >> 3;                // 0..31
    const int kg = (tid & 7) * 4;           // 0..28
    unsigned short hb[4];
    #pragma unroll
    for (int j = 0; j < 4; j++)
        hb[j] = __half_as_ushort(__float2half_rn(t[kg + j][n]));  // stride-33: conflict-free
    const size_t o = (size_t)b * NN * KK + (size_t)(n0 + n) * KK + k0 + kg;
    *reinterpret_cast<ushort4*>(g_Bh + o) = make_ushort4(hb[0], hb[1], hb[2], hb[3]);
}

// ---------------------------------------------------------------------------
// Kernel 3: fp16 split-2 GEMM via mma.sync (m16n8k16).
//   CTA tile 128(M) x 128(N), K-chunk 32, 8 warps (2x4), warp tile 64x32.
//   3-stage cp.async pipeline (R7 schedule), 24 KB/stage -> 72 KB -> 2 CTA/SM.
// ---------------------------------------------------------------------------
#define GM 128
#define GN 128
#define GK 32
#define KCHUNKS (KK / GK)            // 64
#define NSTAGE 3

// Stage layout (SW64-swizzled 64-byte rows):
//   AHI [128][64B], ALO [128][64B], BH [128][64B]
#define OFF_AHI 0
#define OFF_ALO 8192
#define OFF_BH  16384
#define STAGE_BYTES 24576            // 24 KB
#define GEMM_SMEM (NSTAGE * STAGE_BYTES)  // 72 KB

__device__ __forceinline__ void load_stage(uint32_t sbase,
                                           const __half* Ah, const __half* Al,
                                           const __half* Bh,
                                           int k0, int tid) {
    // each array: 128 rows x 4 x 16B chunks = 512 chunks; 2 per thread per array
    #pragma unroll
    for (int t = 0; t < 2; t++) {
        const int c = tid + t * 256;
        const int r = c >> 2, kc = c & 3;
        const uint32_t off = SMEM_SWIZZLE_64B((uint32_t)(r * 64 + kc * 16));
        const size_t gofs = (size_t)r * KK + k0 + kc * 8;    // fp16 elements
        cp16(sbase + OFF_AHI + off, Ah + gofs);
        cp16(sbase + OFF_ALO + off, Al + gofs);
        cp16(sbase + OFF_BH  + off, Bh + gofs);
    }
}

__global__ __launch_bounds__(256, 2)
void gemm_kernel(float* __restrict__ C) {
    extern __shared__ __align__(1024) char smem[];
    const uint32_t sb = smem_u32(smem);
    const int tid  = threadIdx.x;
    const int wid  = tid >> 5;
    const int lane = tid & 31;
    const int wm   = wid >> 2;           // 0..1  -> m offset wm*64
    const int wn   = wid & 3;            // 0..3  -> n offset wn*32
    const int b  = blockIdx.z;
    const int m0 = blockIdx.y * GM;
    const int n0 = blockIdx.x * GN;

    const __half* Ah = g_Ahi + (size_t)b * MM * KK + (size_t)m0 * KK;
    const __half* Al = g_Alo + (size_t)b * MM * KK + (size_t)m0 * KK;
    const __half* Bh = g_Bh  + (size_t)b * NN * KK + (size_t)n0 * KK;

    float acc[4][4][4];                  // [m-tile][n-tile][frag]
    #pragma unroll
    for (int i = 0; i < 4; i++)
        #pragma unroll
        for (int j = 0; j < 4; j++)
            #pragma unroll
            for (int r = 0; r < 4; r++) acc[i][j][r] = 0.0f;

    const int lrow  = lane & 15;
    const int lhalf = lane >> 4;         // 0/1 -> +0 / +8 k-elements (16B)

    // prologue: fill all three stages
    load_stage(sb + 0 * STAGE_BYTES, Ah, Al, Bh, 0 * GK, tid);
    asm volatile("cp.async.commit_group;" ::: "memory");
    load_stage(sb + 1 * STAGE_BYTES, Ah, Al, Bh, 1 * GK, tid);
    asm volatile("cp.async.commit_group;" ::: "memory");
    load_stage(sb + 2 * STAGE_BYTES, Ah, Al, Bh, 2 * GK, tid);
    asm volatile("cp.async.commit_group;" ::: "memory");

    int stage = 0;
    for (int it = 0; it < KCHUNKS; it++) {
        const uint32_t sbase = sb + stage * STAGE_BYTES;

        if      (it < KCHUNKS - 2)  asm volatile("cp.async.wait_group 2;" ::: "memory");
        else if (it == KCHUNKS - 2) asm volatile("cp.async.wait_group 1;" ::: "memory");
        else                        asm volatile("cp.async.wait_group 0;" ::: "memory");
        __syncthreads();

        #pragma unroll
        for (int ks = 0; ks < 2; ks++) {     // 2 x k16 steps per 32-chunk
            const uint32_t bytecol = (uint32_t)(ks * 32 + lhalf * 16);

            uint32_t ahi[4][4], alo[4][4], bb[2][4];
            #pragma unroll
            for (int mt = 0; mt < 4; mt++) {
                const uint32_t off = SMEM_SWIZZLE_64B(
                    (uint32_t)((wm * 64 + mt * 16 + lrow) * 64) + bytecol);
                ldsm_x4(ahi[mt], sbase + OFF_AHI + off);
                ldsm_x4(alo[mt], sbase + OFF_ALO + off);
            }
            #pragma unroll
            for (int nt2 = 0; nt2 < 2; nt2++) {
                const uint32_t off = SMEM_SWIZZLE_64B(
                    (uint32_t)((wn * 32 + nt2 * 16 + lrow) * 64) + bytecol);
                ldsm_x4(bb[nt2], sbase + OFF_BH + off);
            }

            // product 1: Ahi * Bh   (16 MMAs, 16 distinct accumulators)
            #pragma unroll
            for (int mt = 0; mt < 4; mt++)
                #pragma unroll
                for (int nt2 = 0; nt2 < 2; nt2++) {
                    mma_f16(acc[mt][nt2 * 2 + 0], ahi[mt], bb[nt2][0], bb[nt2][2]);
                    mma_f16(acc[mt][nt2 * 2 + 1], ahi[mt], bb[nt2][1], bb[nt2][3]);
                }
            // product 2: Alo * Bh
            #pragma unroll
            for (int mt = 0; mt < 4; mt++)
                #pragma unroll
                for (int nt2 = 0; nt2 < 2; nt2++) {
                    mma_f16(acc[mt][nt2 * 2 + 0], alo[mt], bb[nt2][0], bb[nt2][2]);
                    mma_f16(acc[mt][nt2 * 2 + 1], alo[mt], bb[nt2][1], bb[nt2][3]);
                }
        }
        __syncthreads();

        if (it + NSTAGE < KCHUNKS) {
            load_stage(sbase, Ah, Al, Bh, (it + NSTAGE) * GK, tid);
            asm volatile("cp.async.commit_group;" ::: "memory");
        }
        stage = (stage + 1 == NSTAGE) ? 0 : stage + 1;
    }

    // epilogue: c frag -> rows (lane>>2) and +8, cols (lane&3)*2..+1
    const int crow0 = m0 + wm * 64 + (lane >> 2);
    const int ccol0 = n0 + wn * 32 + (lane & 3) * 2;
    float* Cb = C + (size_t)b * MM * NN;
    #pragma unroll
    for (int mt = 0; mt < 4; mt++) {
        #pragma unroll
        for (int nt = 0; nt < 4; nt++) {
            float* p0 = Cb + (size_t)(crow0 + mt * 16) * NN + ccol0 + nt * 8;
            float* p1 = p0 + 8 * NN;
            *reinterpret_cast<float2*>(p0) = make_float2(acc[mt][nt][0], acc[mt][nt][1]);
            *reinterpret_cast<float2*>(p1) = make_float2(acc[mt][nt][2], acc[mt][nt][3]);
        }
    }
}

// ---------------------------------------------------------------------------
// Launch
// ---------------------------------------------------------------------------
extern "C" void kernel_launch(void* const* d_in, const int* in_sizes, int n_in,
                              void* d_out, int out_size) {
    const float* a = (const float*)d_in[0];
    const float* bsrc = (const float*)d_in[1];
    float* out = (float*)d_out;

    cudaFuncSetAttribute(gemm_kernel, cudaFuncAttributeMaxDynamicSharedMemorySize, GEMM_SMEM);

    convA_fused_kernel<<<BB * MT * KT, 256>>>(a);
    dim3 gb(NN / 32, KK / 32, BB);          // (64, 64, 8)
    convB_kernel<<<gb, 256>>>(bsrc);
    dim3 gg(NN / GN, MM / GM, BB);          // (16, 16, 8)
    gemm_kernel<<<gg, 256, GEMM_SMEM>>>(out);
}

// round 11
// speedup vs baseline: 2.5067x; 1.7562x over previous
#include <cuda_runtime.h>
#include <cuda_fp16.h>
#include <cstdint>

// ---------------------------------------------------------------------------
// Problem shape (fixed by the dataset)
// ---------------------------------------------------------------------------
#define BB 8
#define MM 2048
#define NN 2048
#define KK 2048
#define T64 64
#define MT 32
#define KT 32
#define THRESH 1e-6f

// ---------------------------------------------------------------------------
// Scratch (device globals — no allocation allowed)
//   Single-product fp16: A -> fp16 RN (masked), B -> fp16 RN (transposed).
//   Norm error model: independent RN errors add in quadrature -> ~2.9e-4,
//   3.4x under the 1e-3 gate (measured 2.08e-4 with B-only rounding in R9).
// ---------------------------------------------------------------------------
__device__ __half g_Ah[(size_t)BB * MM * KK];   // [b][m][k]
__device__ __half g_Bh[(size_t)BB * NN * KK];   // transposed: [b][n][k]

// ---------------------------------------------------------------------------
// Helpers
// ---------------------------------------------------------------------------
__device__ __forceinline__ uint32_t smem_u32(const void* p) {
    uint32_t a;
    asm("{ .reg .u64 t; cvta.to.shared.u64 t, %1; cvt.u32.u64 %0, t; }" : "=r"(a) : "l"(p));
    return a;
}
__device__ __forceinline__ void cp16(uint32_t dst, const void* src) {
    asm volatile("cp.async.cg.shared.global [%0], [%1], 16;" :: "r"(dst), "l"(src));
}
// 64-byte-row swizzle (SW64): XOR bits[5:4] with bits[8:7]
#define SMEM_SWIZZLE_64B(off) ((off) ^ (((off) >> 3) & 0x30))

__device__ __forceinline__ void ldsm_x4(uint32_t r[4], uint32_t addr) {
    asm volatile("ldmatrix.sync.aligned.m8n8.x4.shared.b16 {%0,%1,%2,%3}, [%4];"
                 : "=r"(r[0]), "=r"(r[1]), "=r"(r[2]), "=r"(r[3]) : "r"(addr));
}
__device__ __forceinline__ void mma_f16(float c[4], const uint32_t a[4],
                                        uint32_t b0, uint32_t b1) {
    asm volatile(
        "mma.sync.aligned.m16n8k16.row.col.f32.f16.f16.f32 "
        "{%0,%1,%2,%3}, {%4,%5,%6,%7}, {%8,%9}, {%0,%1,%2,%3};"
        : "+f"(c[0]), "+f"(c[1]), "+f"(c[2]), "+f"(c[3])
        : "r"(a[0]), "r"(a[1]), "r"(a[2]), "r"(a[3]), "r"(b0), "r"(b1));
}

// ---------------------------------------------------------------------------
// Kernel 1: fused activity prescan + A conversion (single fp16 RN).
//   One block per 64x64 tile: load tile to regs, block max-reduce |a|,
//   then mask + round + store.  Reads A exactly once.
// ---------------------------------------------------------------------------
__global__ __launch_bounds__(256)
void convA_fused_kernel(const float* __restrict__ a) {
    const int tile = blockIdx.x;
    const int b    = tile / (MT * KT);
    const int rem  = tile % (MT * KT);
    const int mt   = rem / KT;
    const int kt   = rem % KT;
    const size_t gbase = ((size_t)b * MM + (size_t)mt * T64) * KK + (size_t)kt * T64;
    const float* base = a + gbase;

    const int r0 = threadIdx.x >> 4;          // 0..15
    const int c0 = (threadIdx.x & 15) * 4;    // 0..60

    float4 v[4];
    float mx = 0.0f;
    #pragma unroll
    for (int j = 0; j < 4; j++) {
        v[j] = *reinterpret_cast<const float4*>(base + (size_t)(r0 + j * 16) * KK + c0);
        mx = fmaxf(mx, fmaxf(fmaxf(fabsf(v[j].x), fabsf(v[j].y)),
                             fmaxf(fabsf(v[j].z), fabsf(v[j].w))));
    }
    #pragma unroll
    for (int off = 16; off > 0; off >>= 1)
        mx = fmaxf(mx, __shfl_xor_sync(0xFFFFFFFFu, mx, off));

    __shared__ float s[8];
    __shared__ float s_msk;
    if ((threadIdx.x & 31) == 0) s[threadIdx.x >> 5] = mx;
    __syncthreads();
    if (threadIdx.x == 0) {
        float m = s[0];
        #pragma unroll
        for (int w = 1; w < 8; w++) m = fmaxf(m, s[w]);
        s_msk = (m > THRESH) ? 1.0f : 0.0f;
    }
    __syncthreads();
    const float msk = s_msk;

    #pragma unroll
    for (int j = 0; j < 4; j++) {
        unsigned short hb[4];
        hb[0] = __half_as_ushort(__float2half_rn(v[j].x * msk));
        hb[1] = __half_as_ushort(__float2half_rn(v[j].y * msk));
        hb[2] = __half_as_ushort(__float2half_rn(v[j].z * msk));
        hb[3] = __half_as_ushort(__float2half_rn(v[j].w * msk));
        const size_t o = gbase + (size_t)(r0 + j * 16) * KK + c0;
        *reinterpret_cast<ushort4*>(g_Ah + o) = make_ushort4(hb[0], hb[1], hb[2], hb[3]);
    }
}

// ---------------------------------------------------------------------------
// Kernel 2: convert + transpose B: fp32 [b][k][n] -> fp16 [b][n][k]
//   float4 gmem loads, conflict-free padded-smem transpose, ushort4 stores.
// ---------------------------------------------------------------------------
__global__ __launch_bounds__(256)
void convB_kernel(const float* __restrict__ Bsrc) {
    __shared__ float t[32][33];
    const int b  = blockIdx.z;
    const int n0 = blockIdx.x * 32;
    const int k0 = blockIdx.y * 32;
    const int tid = threadIdx.x;

    // load 32x32 fp32 tile: each thread one float4
    {
        const int r  = tid >> 3;            // 0..31 (k-row)
        const int c4 = (tid & 7) * 4;       // n offset
        const float4 v = *reinterpret_cast<const float4*>(
            Bsrc + (size_t)b * KK * NN + (size_t)(k0 + r) * NN + n0 + c4);
        t[r][c4 + 0] = v.x; t[r][c4 + 1] = v.y;
        t[r][c4 + 2] = v.z; t[r][c4 + 3] = v.w;
    }
    __syncthreads();

    // store transposed: each thread handles 4 consecutive k for one n
    const int n  = tid >> 3;                // 0..31
    const int kg = (tid & 7) * 4;           // 0..28
    unsigned short hb[4];
    #pragma unroll
    for (int j = 0; j < 4; j++)
        hb[j] = __half_as_ushort(__float2half_rn(t[kg + j][n]));  // stride-33: conflict-free
    const size_t o = (size_t)b * NN * KK + (size_t)(n0 + n) * KK + k0 + kg;
    *reinterpret_cast<ushort4*>(g_Bh + o) = make_ushort4(hb[0], hb[1], hb[2], hb[3]);
}

// ---------------------------------------------------------------------------
// Kernel 3: single-product fp16 GEMM via mma.sync (m16n8k16).
//   CTA tile 128(M) x 128(N), K-chunk 32, 8 warps (2x4), warp tile 64x32.
//   4-stage cp.async pipeline (R7 schedule shape), 16 KB/stage -> 64 KB.
// ---------------------------------------------------------------------------
#define GM 128
#define GN 128
#define GK 32
#define KCHUNKS (KK / GK)            // 64
#define NSTAGE 4

// Stage layout (SW64-swizzled 64-byte rows): AH [128][64B], BH [128][64B]
#define OFF_AH 0
#define OFF_BH 8192
#define STAGE_BYTES 16384            // 16 KB
#define GEMM_SMEM (NSTAGE * STAGE_BYTES)  // 64 KB

__device__ __forceinline__ void load_stage(uint32_t sbase,
                                           const __half* Ah, const __half* Bh,
                                           int k0, int tid) {
    // each array: 128 rows x 4 x 16B chunks = 512 chunks; 2 per thread per array
    #pragma unroll
    for (int t = 0; t < 2; t++) {
        const int c = tid + t * 256;
        const int r = c >> 2, kc = c & 3;
        const uint32_t off = SMEM_SWIZZLE_64B((uint32_t)(r * 64 + kc * 16));
        const size_t gofs = (size_t)r * KK + k0 + kc * 8;    // fp16 elements
        cp16(sbase + OFF_AH + off, Ah + gofs);
        cp16(sbase + OFF_BH + off, Bh + gofs);
    }
}

__global__ __launch_bounds__(256, 2)
void gemm_kernel(float* __restrict__ C) {
    extern __shared__ __align__(1024) char smem[];
    const uint32_t sb = smem_u32(smem);
    const int tid  = threadIdx.x;
    const int wid  = tid >> 5;
    const int lane = tid & 31;
    const int wm   = wid >> 2;           // 0..1  -> m offset wm*64
    const int wn   = wid & 3;            // 0..3  -> n offset wn*32
    const int b  = blockIdx.z;
    const int m0 = blockIdx.y * GM;
    const int n0 = blockIdx.x * GN;

    const __half* Ah = g_Ah + (size_t)b * MM * KK + (size_t)m0 * KK;
    const __half* Bh = g_Bh + (size_t)b * NN * KK + (size_t)n0 * KK;

    float acc[4][4][4];                  // [m-tile][n-tile][frag]
    #pragma unroll
    for (int i = 0; i < 4; i++)
        #pragma unroll
        for (int j = 0; j < 4; j++)
            #pragma unroll
            for (int r = 0; r < 4; r++) acc[i][j][r] = 0.0f;

    const int lrow  = lane & 15;
    const int lhalf = lane >> 4;         // 0/1 -> +0 / +8 k-elements (16B)

    // prologue: fill all four stages
    #pragma unroll
    for (int p = 0; p < NSTAGE; p++) {
        load_stage(sb + p * STAGE_BYTES, Ah, Bh, p * GK, tid);
        asm volatile("cp.async.commit_group;" ::: "memory");
    }

    int stage = 0;
    for (int it = 0; it < KCHUNKS; it++) {
        const uint32_t sbase = sb + stage * STAGE_BYTES;

        // chunk `it` must be resident; up to NSTAGE-1 newer groups may fly
        if      (it < KCHUNKS - 3)  asm volatile("cp.async.wait_group 3;" ::: "memory");
        else if (it == KCHUNKS - 3) asm volatile("cp.async.wait_group 2;" ::: "memory");
        else if (it == KCHUNKS - 2) asm volatile("cp.async.wait_group 1;" ::: "memory");
        else                        asm volatile("cp.async.wait_group 0;" ::: "memory");
        __syncthreads();

        #pragma unroll
        for (int ks = 0; ks < 2; ks++) {     // 2 x k16 steps per 32-chunk
            const uint32_t bytecol = (uint32_t)(ks * 32 + lhalf * 16);

            uint32_t ah[4][4], bb[2][4];
            #pragma unroll
            for (int mt = 0; mt < 4; mt++) {
                const uint32_t off = SMEM_SWIZZLE_64B(
                    (uint32_t)((wm * 64 + mt * 16 + lrow) * 64) + bytecol);
                ldsm_x4(ah[mt], sbase + OFF_AH + off);
            }
            #pragma unroll
            for (int nt2 = 0; nt2 < 2; nt2++) {
                const uint32_t off = SMEM_SWIZZLE_64B(
                    (uint32_t)((wn * 32 + nt2 * 16 + lrow) * 64) + bytecol);
                ldsm_x4(bb[nt2], sbase + OFF_BH + off);
            }

            // 16 MMAs, 16 distinct accumulators
            #pragma unroll
            for (int mt = 0; mt < 4; mt++)
                #pragma unroll
                for (int nt2 = 0; nt2 < 2; nt2++) {
                    mma_f16(acc[mt][nt2 * 2 + 0], ah[mt], bb[nt2][0], bb[nt2][2]);
                    mma_f16(acc[mt][nt2 * 2 + 1], ah[mt], bb[nt2][1], bb[nt2][3]);
                }
        }
        __syncthreads();

        if (it + NSTAGE < KCHUNKS) {
            load_stage(sbase, Ah, Bh, (it + NSTAGE) * GK, tid);
            asm volatile("cp.async.commit_group;" ::: "memory");
        }
        stage = (stage + 1 == NSTAGE) ? 0 : stage + 1;
    }

    // epilogue: c frag -> rows (lane>>2) and +8, cols (lane&3)*2..+1
    const int crow0 = m0 + wm * 64 + (lane >> 2);
    const int ccol0 = n0 + wn * 32 + (lane & 3) * 2;
    float* Cb = C + (size_t)b * MM * NN;
    #pragma unroll
    for (int mt = 0; mt < 4; mt++) {
        #pragma unroll
        for (int nt = 0; nt < 4; nt++) {
            float* p0 = Cb + (size_t)(crow0 + mt * 16) * NN + ccol0 + nt * 8;
            float* p1 = p0 + 8 * NN;
            *reinterpret_cast<float2*>(p0) = make_float2(acc[mt][nt][0], acc[mt][nt][1]);
            *reinterpret_cast<float2*>(p1) = make_float2(acc[mt][nt][2], acc[mt][nt][3]);
        }
    }
}

// ---------------------------------------------------------------------------
// Launch
// ---------------------------------------------------------------------------
extern "C" void kernel_launch(void* const* d_in, const int* in_sizes, int n_in,
                              void* d_out, int out_size) {
    const float* a = (const float*)d_in[0];
    const float* bsrc = (const float*)d_in[1];
    float* out = (float*)d_out;

    cudaFuncSetAttribute(gemm_kernel, cudaFuncAttributeMaxDynamicSharedMemorySize, GEMM_SMEM);

    convA_fused_kernel<<<BB * MT * KT, 256>>>(a);
    dim3 gb(NN / 32, KK / 32, BB);          // (64, 64, 8)
    convB_kernel<<<gb, 256>>>(bsrc);
    dim3 gg(NN / GN, MM / GM, BB);          // (16, 16, 8)
    gemm_kernel<<<gg, 256, GEMM_SMEM>>>(out);
}

// round 12
// speedup vs baseline: 2.7238x; 1.0866x over previous
#include <cuda_runtime.h>
#include <cuda_fp16.h>
#include <cstdint>

// ---------------------------------------------------------------------------
// Problem shape (fixed by the dataset)
// ---------------------------------------------------------------------------
#define BB 8
#define MM 2048
#define NN 2048
#define KK 2048
#define T64 64
#define MT 32
#define KT 32
#define THRESH 1e-6f

// ---------------------------------------------------------------------------
// Scratch (device globals — no allocation allowed)
//   Single-product fp16: A -> fp16 RN (masked), B -> fp16 RN (transposed).
//   Quadrature error model validated: R9 2.08e-4 (B only), R11 2.94e-4 (both).
// ---------------------------------------------------------------------------
__device__ __half g_Ah[(size_t)BB * MM * KK];   // [b][m][k]
__device__ __half g_Bh[(size_t)BB * NN * KK];   // transposed: [b][n][k]

// ---------------------------------------------------------------------------
// Helpers
// ---------------------------------------------------------------------------
__device__ __forceinline__ uint32_t smem_u32(const void* p) {
    uint32_t a;
    asm("{ .reg .u64 t; cvta.to.shared.u64 t, %1; cvt.u32.u64 %0, t; }" : "=r"(a) : "l"(p));
    return a;
}
__device__ __forceinline__ void cp16(uint32_t dst, const void* src) {
    asm volatile("cp.async.cg.shared.global [%0], [%1], 16;" :: "r"(dst), "l"(src));
}
// 128-byte-row swizzle (SW128): XOR bits[6:4] with bits[9:7]
#define SMEM_SWIZZLE_128B(off) ((off) ^ (((off) >> 3) & 0x70))

__device__ __forceinline__ void ldsm_x4(uint32_t r[4], uint32_t addr) {
    asm volatile("ldmatrix.sync.aligned.m8n8.x4.shared.b16 {%0,%1,%2,%3}, [%4];"
                 : "=r"(r[0]), "=r"(r[1]), "=r"(r[2]), "=r"(r[3]) : "r"(addr));
}
__device__ __forceinline__ void mma_f16(float c[4], const uint32_t a[4],
                                        uint32_t b0, uint32_t b1) {
    asm volatile(
        "mma.sync.aligned.m16n8k16.row.col.f32.f16.f16.f32 "
        "{%0,%1,%2,%3}, {%4,%5,%6,%7}, {%8,%9}, {%0,%1,%2,%3};"
        : "+f"(c[0]), "+f"(c[1]), "+f"(c[2]), "+f"(c[3])
        : "r"(a[0]), "r"(a[1]), "r"(a[2]), "r"(a[3]), "r"(b0), "r"(b1));
}

// ---------------------------------------------------------------------------
// Kernel 1: fused activity prescan + A conversion (single fp16 RN).
// ---------------------------------------------------------------------------
__global__ __launch_bounds__(256)
void convA_fused_kernel(const float* __restrict__ a) {
    const int tile = blockIdx.x;
    const int b    = tile / (MT * KT);
    const int rem  = tile % (MT * KT);
    const int mt   = rem / KT;
    const int kt   = rem % KT;
    const size_t gbase = ((size_t)b * MM + (size_t)mt * T64) * KK + (size_t)kt * T64;
    const float* base = a + gbase;

    const int r0 = threadIdx.x >> 4;          // 0..15
    const int c0 = (threadIdx.x & 15) * 4;    // 0..60

    float4 v[4];
    float mx = 0.0f;
    #pragma unroll
    for (int j = 0; j < 4; j++) {
        v[j] = *reinterpret_cast<const float4*>(base + (size_t)(r0 + j * 16) * KK + c0);
        mx = fmaxf(mx, fmaxf(fmaxf(fabsf(v[j].x), fabsf(v[j].y)),
                             fmaxf(fabsf(v[j].z), fabsf(v[j].w))));
    }
    #pragma unroll
    for (int off = 16; off > 0; off >>= 1)
        mx = fmaxf(mx, __shfl_xor_sync(0xFFFFFFFFu, mx, off));

    __shared__ float s[8];
    __shared__ float s_msk;
    if ((threadIdx.x & 31) == 0) s[threadIdx.x >> 5] = mx;
    __syncthreads();
    if (threadIdx.x == 0) {
        float m = s[0];
        #pragma unroll
        for (int w = 1; w < 8; w++) m = fmaxf(m, s[w]);
        s_msk = (m > THRESH) ? 1.0f : 0.0f;
    }
    __syncthreads();
    const float msk = s_msk;

    #pragma unroll
    for (int j = 0; j < 4; j++) {
        unsigned short hb[4];
        hb[0] = __half_as_ushort(__float2half_rn(v[j].x * msk));
        hb[1] = __half_as_ushort(__float2half_rn(v[j].y * msk));
        hb[2] = __half_as_ushort(__float2half_rn(v[j].z * msk));
        hb[3] = __half_as_ushort(__float2half_rn(v[j].w * msk));
        const size_t o = gbase + (size_t)(r0 + j * 16) * KK + c0;
        *reinterpret_cast<ushort4*>(g_Ah + o) = make_ushort4(hb[0], hb[1], hb[2], hb[3]);
    }
}

// ---------------------------------------------------------------------------
// Kernel 2: convert + transpose B: fp32 [b][k][n] -> fp16 [b][n][k]
// ---------------------------------------------------------------------------
__global__ __launch_bounds__(256)
void convB_kernel(const float* __restrict__ Bsrc) {
    __shared__ float t[32][33];
    const int b  = blockIdx.z;
    const int n0 = blockIdx.x * 32;
    const int k0 = blockIdx.y * 32;
    const int tid = threadIdx.x;

    // load 32x32 fp32 tile: each thread one float4
    {
        const int r  = tid >> 3;            // 0..31 (k-row)
        const int c4 = (tid & 7) * 4;       // n offset
        const float4 v = *reinterpret_cast<const float4*>(
            Bsrc + (size_t)b * KK * NN + (size_t)(k0 + r) * NN + n0 + c4);
        t[r][c4 + 0] = v.x; t[r][c4 + 1] = v.y;
        t[r][c4 + 2] = v.z; t[r][c4 + 3] = v.w;
    }
    __syncthreads();

    // store transposed: each thread handles 4 consecutive k for one n
    const int n  = tid >> 3;                // 0..31
    const int kg = (tid & 7) * 4;           // 0..28
    unsigned short hb[4];
    #pragma unroll
    for (int j = 0; j < 4; j++)
        hb[j] = __half_as_ushort(__float2half_rn(t[kg + j][n]));  // stride-33: conflict-free
    const size_t o = (size_t)b * NN * KK + (size_t)(n0 + n) * KK + k0 + kg;
    *reinterpret_cast<ushort4*>(g_Bh + o) = make_ushort4(hb[0], hb[1], hb[2], hb[3]);
}

// ---------------------------------------------------------------------------
// Kernel 3: single-product fp16 GEMM via mma.sync (m16n8k16).
//   CTA tile 128(M) x 128(N), K-chunk 64, 8 warps (2x4), warp tile 64x32.
//   3-stage cp.async pipeline, 32 KB/stage -> 96 KB -> 2 CTA/SM.
//   Half the barrier/wait overhead of the GK=32 version; 4-step unroll
//   lets ptxas software-pipeline LDSMs under the MMA bursts.
// ---------------------------------------------------------------------------
#define GM 128
#define GN 128
#define GK 64
#define KCHUNKS (KK / GK)            // 32
#define NSTAGE 3

// Stage layout (SW128-swizzled 128-byte rows): AH [128][128B], BH [128][128B]
#define OFF_AH 0
#define OFF_BH 16384
#define STAGE_BYTES 32768            // 32 KB
#define GEMM_SMEM (NSTAGE * STAGE_BYTES)  // 96 KB

__device__ __forceinline__ void load_stage(uint32_t sbase,
                                           const __half* Ah, const __half* Bh,
                                           int k0, int tid) {
    // each array: 128 rows x 8 x 16B chunks = 1024 chunks; 4 per thread per array
    #pragma unroll
    for (int t = 0; t < 4; t++) {
        const int c = tid + t * 256;
        const int r = c >> 3, kc = c & 7;
        const uint32_t off = SMEM_SWIZZLE_128B((uint32_t)(r * 128 + kc * 16));
        const size_t gofs = (size_t)r * KK + k0 + kc * 8;    // fp16 elements
        cp16(sbase + OFF_AH + off, Ah + gofs);
        cp16(sbase + OFF_BH + off, Bh + gofs);
    }
}

__global__ __launch_bounds__(256, 2)
void gemm_kernel(float* __restrict__ C) {
    extern __shared__ __align__(1024) char smem[];
    const uint32_t sb = smem_u32(smem);
    const int tid  = threadIdx.x;
    const int wid  = tid >> 5;
    const int lane = tid & 31;
    const int wm   = wid >> 2;           // 0..1  -> m offset wm*64
    const int wn   = wid & 3;            // 0..3  -> n offset wn*32
    const int b  = blockIdx.z;
    const int m0 = blockIdx.y * GM;
    const int n0 = blockIdx.x * GN;

    const __half* Ah = g_Ah + (size_t)b * MM * KK + (size_t)m0 * KK;
    const __half* Bh = g_Bh + (size_t)b * NN * KK + (size_t)n0 * KK;

    float acc[4][4][4];                  // [m-tile][n-tile][frag]
    #pragma unroll
    for (int i = 0; i < 4; i++)
        #pragma unroll
        for (int j = 0; j < 4; j++)
            #pragma unroll
            for (int r = 0; r < 4; r++) acc[i][j][r] = 0.0f;

    const int lrow  = lane & 15;
    const int lhalf = lane >> 4;         // 0/1 -> +0 / +8 k-elements (16B)

    // prologue: fill all three stages
    #pragma unroll
    for (int p = 0; p < NSTAGE; p++) {
        load_stage(sb + p * STAGE_BYTES, Ah, Bh, p * GK, tid);
        asm volatile("cp.async.commit_group;" ::: "memory");
    }

    int stage = 0;
    for (int it = 0; it < KCHUNKS; it++) {
        const uint32_t sbase = sb + stage * STAGE_BYTES;

        if      (it < KCHUNKS - 2)  asm volatile("cp.async.wait_group 2;" ::: "memory");
        else if (it == KCHUNKS - 2) asm volatile("cp.async.wait_group 1;" ::: "memory");
        else                        asm volatile("cp.async.wait_group 0;" ::: "memory");
        __syncthreads();

        #pragma unroll
        for (int ks = 0; ks < 4; ks++) {     // 4 x k16 steps per 64-chunk
            const uint32_t bytecol = (uint32_t)(ks * 32 + lhalf * 16);

            uint32_t ah[4][4], bb[2][4];
            #pragma unroll
            for (int mt = 0; mt < 4; mt++) {
                const uint32_t off = SMEM_SWIZZLE_128B(
                    (uint32_t)((wm * 64 + mt * 16 + lrow) * 128) + bytecol);
                ldsm_x4(ah[mt], sbase + OFF_AH + off);
            }
            #pragma unroll
            for (int nt2 = 0; nt2 < 2; nt2++) {
                const uint32_t off = SMEM_SWIZZLE_128B(
                    (uint32_t)((wn * 32 + nt2 * 16 + lrow) * 128) + bytecol);
                ldsm_x4(bb[nt2], sbase + OFF_BH + off);
            }

            // 16 MMAs, 16 distinct accumulators
            #pragma unroll
            for (int mt = 0; mt < 4; mt++)
                #pragma unroll
                for (int nt2 = 0; nt2 < 2; nt2++) {
                    mma_f16(acc[mt][nt2 * 2 + 0], ah[mt], bb[nt2][0], bb[nt2][2]);
                    mma_f16(acc[mt][nt2 * 2 + 1], ah[mt], bb[nt2][1], bb[nt2][3]);
                }
        }
        __syncthreads();

        if (it + NSTAGE < KCHUNKS) {
            load_stage(sbase, Ah, Bh, (it + NSTAGE) * GK, tid);
            asm volatile("cp.async.commit_group;" ::: "memory");
        }
        stage = (stage + 1 == NSTAGE) ? 0 : stage + 1;
    }

    // epilogue: c frag -> rows (lane>>2) and +8, cols (lane&3)*2..+1
    const int crow0 = m0 + wm * 64 + (lane >> 2);
    const int ccol0 = n0 + wn * 32 + (lane & 3) * 2;
    float* Cb = C + (size_t)b * MM * NN;
    #pragma unroll
    for (int mt = 0; mt < 4; mt++) {
        #pragma unroll
        for (int nt = 0; nt < 4; nt++) {
            float* p0 = Cb + (size_t)(crow0 + mt * 16) * NN + ccol0 + nt * 8;
            float* p1 = p0 + 8 * NN;
            *reinterpret_cast<float2*>(p0) = make_float2(acc[mt][nt][0], acc[mt][nt][1]);
            *reinterpret_cast<float2*>(p1) = make_float2(acc[mt][nt][2], acc[mt][nt][3]);
        }
    }
}

// ---------------------------------------------------------------------------
// Launch
// ---------------------------------------------------------------------------
extern "C" void kernel_launch(void* const* d_in, const int* in_sizes, int n_in,
                              void* d_out, int out_size) {
    const float* a = (const float*)d_in[0];
    const float* bsrc = (const float*)d_in[1];
    float* out = (float*)d_out;

    cudaFuncSetAttribute(gemm_kernel, cudaFuncAttributeMaxDynamicSharedMemorySize, GEMM_SMEM);

    convA_fused_kernel<<<BB * MT * KT, 256>>>(a);
    dim3 gb(NN / 32, KK / 32, BB);          // (64, 64, 8)
    convB_kernel<<<gb, 256>>>(bsrc);
    dim3 gg(NN / GN, MM / GM, BB);          // (16, 16, 8)
    gemm_kernel<<<gg, 256, GEMM_SMEM>>>(out);
}

// round 14
// speedup vs baseline: 2.7606x; 1.0135x over previous
#include <cuda_runtime.h>
#include <cuda_fp16.h>
#include <cstdint>

// ---------------------------------------------------------------------------
// Problem shape (fixed by the dataset)
// ---------------------------------------------------------------------------
#define BB 8
#define MM 2048
#define NN 2048
#define KK 2048
#define T64 64
#define MT 32
#define KT 32
#define THRESH 1e-6f

// ---------------------------------------------------------------------------
// Scratch (device globals — no allocation allowed)
//   Single-product fp16: A -> fp16 RN (masked), B -> fp16 RN (transposed).
//   Quadrature error model validated: R9 2.08e-4 (B only), R11/12 2.94e-4.
// ---------------------------------------------------------------------------
__device__ __half g_Ah[(size_t)BB * MM * KK];   // [b][m][k]
__device__ __half g_Bh[(size_t)BB * NN * KK];   // transposed: [b][n][k]

// ---------------------------------------------------------------------------
// Helpers
// ---------------------------------------------------------------------------
__device__ __forceinline__ uint32_t smem_u32(const void* p) {
    uint32_t a;
    asm("{ .reg .u64 t; cvta.to.shared.u64 t, %1; cvt.u32.u64 %0, t; }" : "=r"(a) : "l"(p));
    return a;
}
__device__ __forceinline__ void cp16(uint32_t dst, const void* src) {
    asm volatile("cp.async.cg.shared.global [%0], [%1], 16;" :: "r"(dst), "l"(src));
}
// 128-byte-row swizzle (SW128): XOR bits[6:4] with bits[9:7]
#define SMEM_SWIZZLE_128B(off) ((off) ^ (((off) >> 3) & 0x70))

__device__ __forceinline__ void ldsm_x4(uint32_t r[4], uint32_t addr) {
    asm volatile("ldmatrix.sync.aligned.m8n8.x4.shared.b16 {%0,%1,%2,%3}, [%4];"
                 : "=r"(r[0]), "=r"(r[1]), "=r"(r[2]), "=r"(r[3]) : "r"(addr));
}
__device__ __forceinline__ void mma_f16(float c[4], const uint32_t a[4],
                                        uint32_t b0, uint32_t b1) {
    asm volatile(
        "mma.sync.aligned.m16n8k16.row.col.f32.f16.f16.f32 "
        "{%0,%1,%2,%3}, {%4,%5,%6,%7}, {%8,%9}, {%0,%1,%2,%3};"
        : "+f"(c[0]), "+f"(c[1]), "+f"(c[2]), "+f"(c[3])
        : "r"(a[0]), "r"(a[1]), "r"(a[2]), "r"(a[3]), "r"(b0), "r"(b1));
}

// ---------------------------------------------------------------------------
// Kernel 1: fused activity prescan + A conversion (single fp16 RN).
// ---------------------------------------------------------------------------
__global__ __launch_bounds__(256)
void convA_fused_kernel(const float* __restrict__ a) {
    const int tile = blockIdx.x;
    const int b    = tile / (MT * KT);
    const int rem  = tile % (MT * KT);
    const int mt   = rem / KT;
    const int kt   = rem % KT;
    const size_t gbase = ((size_t)b * MM + (size_t)mt * T64) * KK + (size_t)kt * T64;
    const float* base = a + gbase;

    const int r0 = threadIdx.x >> 4;          // 0..15
    const int c0 = (threadIdx.x & 15) * 4;    // 0..60

    float4 v[4];
    float mx = 0.0f;
    #pragma unroll
    for (int j = 0; j < 4; j++) {
        v[j] = *reinterpret_cast<const float4*>(base + (size_t)(r0 + j * 16) * KK + c0);
        mx = fmaxf(mx, fmaxf(fmaxf(fabsf(v[j].x), fabsf(v[j].y)),
                             fmaxf(fabsf(v[j].z), fabsf(v[j].w))));
    }
    #pragma unroll
    for (int off = 16; off > 0; off >>= 1)
        mx = fmaxf(mx, __shfl_xor_sync(0xFFFFFFFFu, mx, off));

    __shared__ float s[8];
    __shared__ float s_msk;
    if ((threadIdx.x & 31) == 0) s[threadIdx.x >> 5] = mx;
    __syncthreads();
    if (threadIdx.x == 0) {
        float m = s[0];
        #pragma unroll
        for (int w = 1; w < 8; w++) m = fmaxf(m, s[w]);
        s_msk = (m > THRESH) ? 1.0f : 0.0f;
    }
    __syncthreads();
    const float msk = s_msk;

    #pragma unroll
    for (int j = 0; j < 4; j++) {
        unsigned short hb[4];
        hb[0] = __half_as_ushort(__float2half_rn(v[j].x * msk));
        hb[1] = __half_as_ushort(__float2half_rn(v[j].y * msk));
        hb[2] = __half_as_ushort(__float2half_rn(v[j].z * msk));
        hb[3] = __half_as_ushort(__float2half_rn(v[j].w * msk));
        const size_t o = gbase + (size_t)(r0 + j * 16) * KK + c0;
        *reinterpret_cast<ushort4*>(g_Ah + o) = make_ushort4(hb[0], hb[1], hb[2], hb[3]);
    }
}

// ---------------------------------------------------------------------------
// Kernel 2: convert + transpose B: fp32 [b][k][n] -> fp16 [b][n][k]
//   64x64 tiles, 4x float4 loads + 4x ushort4 stores per thread (MLP 4),
//   transposed writes coalesce 128B across 4 lanes.
// ---------------------------------------------------------------------------
__global__ __launch_bounds__(256)
void convB_kernel(const float* __restrict__ Bsrc) {
    __shared__ float t[64][65];
    const int b  = blockIdx.z;
    const int n0 = blockIdx.x * 64;
    const int k0 = blockIdx.y * 64;
    const int tid = threadIdx.x;

    // load 64x64 fp32 tile: each thread 4 float4s (rows r, r+16, r+32, r+48)
    {
        const int r  = tid >> 4;            // 0..15 (k-row base)
        const int c4 = (tid & 15) * 4;      // n offset
        const float* src = Bsrc + (size_t)b * KK * NN + (size_t)k0 * NN + n0;
        #pragma unroll
        for (int j = 0; j < 4; j++) {
            const float4 v = *reinterpret_cast<const float4*>(src + (size_t)(r + j * 16) * NN + c4);
            t[r + j * 16][c4 + 0] = v.x; t[r + j * 16][c4 + 1] = v.y;
            t[r + j * 16][c4 + 2] = v.z; t[r + j * 16][c4 + 3] = v.w;
        }
    }
    __syncthreads();

    // store transposed: thread -> (n = tid>>2, k block of 16 = (tid&3)*16)
    // 4 lanes cover 64 consecutive k for one n -> 128B coalesced per n.
    const int n  = tid >> 2;                // 0..63
    const int kq = (tid & 3) * 16;          // 0, 16, 32, 48
    __half* dst = g_Bh + (size_t)b * NN * KK + (size_t)(n0 + n) * KK + k0 + kq;
    #pragma unroll
    for (int g = 0; g < 4; g++) {
        unsigned short hb[4];
        #pragma unroll
        for (int j = 0; j < 4; j++)
            hb[j] = __half_as_ushort(__float2half_rn(t[kq + g * 4 + j][n]));
        *reinterpret_cast<ushort4*>(dst + g * 4) = make_ushort4(hb[0], hb[1], hb[2], hb[3]);
    }
}

// ---------------------------------------------------------------------------
// Kernel 3: single-product fp16 GEMM via mma.sync (m16n8k16).
//   CTA tile 128(M) x 128(N), K-chunk 64, 8 warps (2x4), warp tile 64x32.
//   3 slots / prefetch-depth-2 cp.async pipeline, ONE barrier per iteration;
//   refill issued AFTER the MMA burst (avoids R8's LSU front-loading).
// ---------------------------------------------------------------------------
#define GM 128
#define GN 128
#define GK 64
#define KCHUNKS (KK / GK)            // 32
#define NSTAGE 3

// Stage layout (SW128-swizzled 128-byte rows): AH [128][128B], BH [128][128B]
#define OFF_AH 0
#define OFF_BH 16384
#define STAGE_BYTES 32768            // 32 KB
#define GEMM_SMEM (NSTAGE * STAGE_BYTES)  // 96 KB

__device__ __forceinline__ void load_stage(uint32_t sbase,
                                           const __half* Ah, const __half* Bh,
                                           int k0, int tid) {
    // each array: 128 rows x 8 x 16B chunks = 1024 chunks; 4 per thread per array
    #pragma unroll
    for (int t = 0; t < 4; t++) {
        const int c = tid + t * 256;
        const int r = c >> 3, kc = c & 7;
        const uint32_t off = SMEM_SWIZZLE_128B((uint32_t)(r * 128 + kc * 16));
        const size_t gofs = (size_t)r * KK + k0 + kc * 8;    // fp16 elements
        cp16(sbase + OFF_AH + off, Ah + gofs);
        cp16(sbase + OFF_BH + off, Bh + gofs);
    }
}

__global__ __launch_bounds__(256, 2)
void gemm_kernel(float* __restrict__ C) {
    extern __shared__ __align__(1024) char smem[];
    const uint32_t sb = smem_u32(smem);
    const int tid  = threadIdx.x;
    const int wid  = tid >> 5;
    const int lane = tid & 31;
    const int wm   = wid >> 2;           // 0..1  -> m offset wm*64
    const int wn   = wid & 3;            // 0..3  -> n offset wn*32
    const int b  = blockIdx.z;
    const int m0 = blockIdx.y * GM;
    const int n0 = blockIdx.x * GN;

    const __half* Ah = g_Ah + (size_t)b * MM * KK + (size_t)m0 * KK;
    const __half* Bh = g_Bh + (size_t)b * NN * KK + (size_t)n0 * KK;

    float acc[4][4][4];                  // [m-tile][n-tile][frag]
    #pragma unroll
    for (int i = 0; i < 4; i++)
        #pragma unroll
        for (int j = 0; j < 4; j++)
            #pragma unroll
            for (int r = 0; r < 4; r++) acc[i][j][r] = 0.0f;

    const int lrow  = lane & 15;
    const int lhalf = lane >> 4;         // 0/1 -> +0 / +8 k-elements (16B)

    // prologue: prefetch depth 2 (chunks 0 and 1 into slots 0 and 1)
    load_stage(sb + 0 * STAGE_BYTES, Ah, Bh, 0 * GK, tid);
    asm volatile("cp.async.commit_group;" ::: "memory");
    load_stage(sb + 1 * STAGE_BYTES, Ah, Bh, 1 * GK, tid);
    asm volatile("cp.async.commit_group;" ::: "memory");

    int stage = 0;           // slot of chunk `it`   (chunk c -> slot c % 3)
    int fill  = 2;           // slot for chunk `it+2` (consumed at it-1)
    for (int it = 0; it < KCHUNKS; it++) {
        const uint32_t sbase = sb + stage * STAGE_BYTES;

        // chunk `it` resident; chunk `it+1` may still fly
        if (it + 2 < KCHUNKS) asm volatile("cp.async.wait_group 1;" ::: "memory");
        else                  asm volatile("cp.async.wait_group 0;" ::: "memory");
        // single barrier: data-ready AND all warps finished reading slot `fill`
        // (it held chunk it-1 last iteration)
        __syncthreads();

        #pragma unroll
        for (int ks = 0; ks < 4; ks++) {     // 4 x k16 steps per 64-chunk
            const uint32_t bytecol = (uint32_t)(ks * 32 + lhalf * 16);

            uint32_t ah[4][4], bb[2][4];
            #pragma unroll
            for (int mt = 0; mt < 4; mt++) {
                const uint32_t off = SMEM_SWIZZLE_128B(
                    (uint32_t)((wm * 64 + mt * 16 + lrow) * 128) + bytecol);
                ldsm_x4(ah[mt], sbase + OFF_AH + off);
            }
            #pragma unroll
            for (int nt2 = 0; nt2 < 2; nt2++) {
                const uint32_t off = SMEM_SWIZZLE_128B(
                    (uint32_t)((wn * 32 + nt2 * 16 + lrow) * 128) + bytecol);
                ldsm_x4(bb[nt2], sbase + OFF_BH + off);
            }

            // 16 MMAs, 16 distinct accumulators
            #pragma unroll
            for (int mt = 0; mt < 4; mt++)
                #pragma unroll
                for (int nt2 = 0; nt2 < 2; nt2++) {
                    mma_f16(acc[mt][nt2 * 2 + 0], ah[mt], bb[nt2][0], bb[nt2][2]);
                    mma_f16(acc[mt][nt2 * 2 + 1], ah[mt], bb[nt2][1], bb[nt2][3]);
                }
        }

        // refill AFTER compute: safety proven by this iteration's top barrier
        if (it + 2 < KCHUNKS) {
            load_stage(sb + fill * STAGE_BYTES, Ah, Bh, (it + 2) * GK, tid);
            asm volatile("cp.async.commit_group;" ::: "memory");
        }

        stage = (stage + 1 == NSTAGE) ? 0 : stage + 1;
        fill  = (fill  + 1 == NSTAGE) ? 0 : fill  + 1;
    }

    // epilogue: c frag -> rows (lane>>2) and +8, cols (lane&3)*2..+1
    const int crow0 = m0 + wm * 64 + (lane >> 2);
    const int ccol0 = n0 + wn * 32 + (lane & 3) * 2;
    float* Cb = C + (size_t)b * MM * NN;
    #pragma unroll
    for (int mt = 0; mt < 4; mt++) {
        #pragma unroll
        for (int nt = 0; nt < 4; nt++) {
            float* p0 = Cb + (size_t)(crow0 + mt * 16) * NN + ccol0 + nt * 8;
            float* p1 = p0 + 8 * NN;
            *reinterpret_cast<float2*>(p0) = make_float2(acc[mt][nt][0], acc[mt][nt][1]);
            *reinterpret_cast<float2*>(p1) = make_float2(acc[mt][nt][2], acc[mt][nt][3]);
        }
    }
}

// ---------------------------------------------------------------------------
// Launch
// ---------------------------------------------------------------------------
extern "C" void kernel_launch(void* const* d_in, const int* in_sizes, int n_in,
                              void* d_out, int out_size) {
    const float* a = (const float*)d_in[0];
    const float* bsrc = (const float*)d_in[1];
    float* out = (float*)d_out;

    cudaFuncSetAttribute(gemm_kernel, cudaFuncAttributeMaxDynamicSharedMemorySize, GEMM_SMEM);

    convA_fused_kernel<<<BB * MT * KT, 256>>>(a);
    dim3 gb(NN / 64, KK / 64, BB);          // (32, 32, 8)
    convB_kernel<<<gb, 256>>>(bsrc);
    dim3 gg(NN / GN, MM / GM, BB);          // (16, 16, 8)
    gemm_kernel<<<gg, 256, GEMM_SMEM>>>(out);
}